// round 10
// baseline (speedup 1.0000x reference)
#include <cuda_runtime.h>
#include <math.h>

#define KDIM 64
#define DEG 32
#define N0_MAX 65536

// hop-0 aggregate scratch: 65536 x 64 f32 = 16 MB (static __device__, no alloc)
__device__ __align__(256) float g_agg0[N0_MAX * KDIM];

// reduce across 8 lanes (xor 4,2,1) — quarter-warp
__device__ __forceinline__ float quarter_sum(float v) {
#pragma unroll
    for (int o = 4; o > 0; o >>= 1) v += __shfl_xor_sync(0xffffffffu, v, o);
    return v;
}
// reduce across a 16-lane half-warp (xor 8,4,2,1)
__device__ __forceinline__ float half_sum(float v) {
#pragma unroll
    for (int o = 8; o > 0; o >>= 1) v += __shfl_xor_sync(0xffffffffu, v, o);
    return v;
}

// renorm scale: min(1, 1/max(sqrt(ss), 1e-12)) == ss > 1 ? rsqrt(ss) : 1
__device__ __forceinline__ float renorm_scale(float ss) {
    return (ss > 1.0f) ? rsqrtf(ss) : 1.0f;
}

// 256-bit (32B) read-only global load — one instruction, 8 floats.
__device__ __forceinline__ void ldg256(const float* p, float4& a, float4& b) {
    unsigned r0, r1, r2, r3, r4, r5, r6, r7;
    asm volatile("ld.global.nc.v8.b32 {%0,%1,%2,%3,%4,%5,%6,%7}, [%8];"
                 : "=r"(r0), "=r"(r1), "=r"(r2), "=r"(r3),
                   "=r"(r4), "=r"(r5), "=r"(r6), "=r"(r7)
                 : "l"(p));
    a.x = __uint_as_float(r0); a.y = __uint_as_float(r1);
    a.z = __uint_as_float(r2); a.w = __uint_as_float(r3);
    b.x = __uint_as_float(r4); b.y = __uint_as_float(r5);
    b.z = __uint_as_float(r6); b.w = __uint_as_float(r7);
}

// ============================ hop 0 ============================
// One warp per node. Quarter-warp qw (8 lanes) covers neighbors {8*qw+i};
// lane ql owns dims [8*ql, 8*ql+8) via ONE 256-bit load per row.
// 8 passes x 4 rows-in-flight; per-row norm reduce is 3 shuffles.
__global__ void __launch_bounds__(128) hop0_kernel(
    const float* __restrict__ entity_emb,
    const int* __restrict__ node_ids0,
    const int* __restrict__ nbr0,
    int n0)
{
    const int node = blockIdx.x * (blockDim.x >> 5) + (threadIdx.x >> 5);
    const int lane = threadIdx.x & 31;
    const int qw   = lane >> 3;          // quarter-warp id (0..3)
    const int ql   = lane & 7;           // lane within quarter
    if (node >= n0) return;

    const int myidx = __ldg(nbr0 + (size_t)node * DEG + lane);
    const int tid   = __ldg(node_ids0 + node);

    // ---- batched prefetch: 8 rows per quarter-warp, 32B per lane per row ----
    float4 ea[8], eb[8];
#pragma unroll
    for (int i = 0; i < 8; i++) {
        const int id = __shfl_sync(0xffffffffu, myidx, (qw << 3) + i);
        ldg256(entity_emb + (size_t)id * KDIM + ql * 8, ea[i], eb[i]);
    }
    float4 ta, tb;
    ldg256(entity_emb + (size_t)tid * KDIM + ql * 8, ta, tb);

    // ---- FM accumulate with per-row renorm (reduce across 8 lanes) ----
    float4 sa = make_float4(0.f, 0.f, 0.f, 0.f), sb = sa;
    float4 qa = sa, qb = sa;
#pragma unroll
    for (int i = 0; i < 8; i++) {
        const float loc = ea[i].x * ea[i].x + ea[i].y * ea[i].y +
                          ea[i].z * ea[i].z + ea[i].w * ea[i].w +
                          eb[i].x * eb[i].x + eb[i].y * eb[i].y +
                          eb[i].z * eb[i].z + eb[i].w * eb[i].w;
        const float sc = renorm_scale(quarter_sum(loc));
        const float ax = ea[i].x * sc, ay = ea[i].y * sc,
                    az = ea[i].z * sc, aw = ea[i].w * sc;
        const float bx = eb[i].x * sc, by = eb[i].y * sc,
                    bz = eb[i].z * sc, bw = eb[i].w * sc;
        sa.x += ax; sa.y += ay; sa.z += az; sa.w += aw;
        sb.x += bx; sb.y += by; sb.z += bz; sb.w += bw;
        qa.x += ax * ax; qa.y += ay * ay; qa.z += az * az; qa.w += aw * aw;
        qb.x += bx * bx; qb.y += by * by; qb.z += bz * bz; qb.w += bw * bw;
    }

    // combine the 4 quarter-warps (same dims at lane ^ 8 and lane ^ 16)
#pragma unroll
    for (int o = 8; o <= 16; o <<= 1) {
        sa.x += __shfl_xor_sync(0xffffffffu, sa.x, o);
        sa.y += __shfl_xor_sync(0xffffffffu, sa.y, o);
        sa.z += __shfl_xor_sync(0xffffffffu, sa.z, o);
        sa.w += __shfl_xor_sync(0xffffffffu, sa.w, o);
        sb.x += __shfl_xor_sync(0xffffffffu, sb.x, o);
        sb.y += __shfl_xor_sync(0xffffffffu, sb.y, o);
        sb.z += __shfl_xor_sync(0xffffffffu, sb.z, o);
        sb.w += __shfl_xor_sync(0xffffffffu, sb.w, o);
        qa.x += __shfl_xor_sync(0xffffffffu, qa.x, o);
        qa.y += __shfl_xor_sync(0xffffffffu, qa.y, o);
        qa.z += __shfl_xor_sync(0xffffffffu, qa.z, o);
        qa.w += __shfl_xor_sync(0xffffffffu, qa.w, o);
        qb.x += __shfl_xor_sync(0xffffffffu, qb.x, o);
        qb.y += __shfl_xor_sync(0xffffffffu, qb.y, o);
        qb.z += __shfl_xor_sync(0xffffffffu, qb.z, o);
        qb.w += __shfl_xor_sync(0xffffffffu, qb.w, o);
    }

    // target renorm (dims split across the 8 lanes of each quarter)
    const float tloc = ta.x * ta.x + ta.y * ta.y + ta.z * ta.z + ta.w * ta.w +
                       tb.x * tb.x + tb.y * tb.y + tb.z * tb.z + tb.w * tb.w;
    const float tsc = renorm_scale(quarter_sum(tloc));

    if (qw == 0) {
        float4 oa, ob;
        oa.x = sa.x * sa.x - qa.x + ta.x * tsc;
        oa.y = sa.y * sa.y - qa.y + ta.y * tsc;
        oa.z = sa.z * sa.z - qa.z + ta.z * tsc;
        oa.w = sa.w * sa.w - qa.w + ta.w * tsc;
        ob.x = sb.x * sb.x - qb.x + tb.x * tsc;
        ob.y = sb.y * sb.y - qb.y + tb.y * tsc;
        ob.z = sb.z * sb.z - qb.z + tb.z * tsc;
        ob.w = sb.w * sb.w - qb.w + tb.w * tsc;
        float4* dst = (float4*)(g_agg0 + (size_t)node * KDIM + ql * 8);
        dst[0] = oa;
        dst[1] = ob;
    }
}

// ============================ hop 1 ============================
// R8 version verbatim (best measured: 7.68us). One BLOCK (4 warps) per row;
// warp w handles neighbors [8w,8w+8), half-warp sub takes 4; smem combine.
__global__ void __launch_bounds__(128) hop1_kernel(
    const float* __restrict__ entity_emb,
    const float* __restrict__ user_emb,
    const int* __restrict__ u,
    const int* __restrict__ item_ids,
    const int* __restrict__ nbr1_idx,
    float* __restrict__ out,
    int B)
{
    __shared__ float4 sm_s[4][16];
    __shared__ float4 sm_q[4][16];

    const int b    = blockIdx.x;
    const int w    = threadIdx.x >> 5;
    const int lane = threadIdx.x & 31;
    const int sub  = lane >> 4;
    const int sl   = lane & 15;
    if (b >= B) return;

    const int myidx = (lane < 8)
        ? __ldg(nbr1_idx + (size_t)b * DEG + w * 8 + lane) : 0;

    float4 e[4];
#pragma unroll
    for (int i = 0; i < 4; i++) {
        const int id = __shfl_sync(0xffffffffu, myidx, (sub << 2) + i);
        e[i] = *((const float4*)(g_agg0 + (size_t)id * KDIM) + sl);
    }

    float4 s = make_float4(0.f, 0.f, 0.f, 0.f);
    float4 q = make_float4(0.f, 0.f, 0.f, 0.f);
#pragma unroll
    for (int i = 0; i < 4; i++) {
        s.x += e[i].x; s.y += e[i].y; s.z += e[i].z; s.w += e[i].w;
        q.x += e[i].x * e[i].x; q.y += e[i].y * e[i].y;
        q.z += e[i].z * e[i].z; q.w += e[i].w * e[i].w;
    }

    s.x += __shfl_xor_sync(0xffffffffu, s.x, 16);
    s.y += __shfl_xor_sync(0xffffffffu, s.y, 16);
    s.z += __shfl_xor_sync(0xffffffffu, s.z, 16);
    s.w += __shfl_xor_sync(0xffffffffu, s.w, 16);
    q.x += __shfl_xor_sync(0xffffffffu, q.x, 16);
    q.y += __shfl_xor_sync(0xffffffffu, q.y, 16);
    q.z += __shfl_xor_sync(0xffffffffu, q.z, 16);
    q.w += __shfl_xor_sync(0xffffffffu, q.w, 16);

    if (sub == 0) { sm_s[w][sl] = s; sm_q[w][sl] = q; }
    __syncthreads();

    if (w == 0) {
        float4 S = sm_s[0][sl], Q = sm_q[0][sl];
#pragma unroll
        for (int j = 1; j < 4; j++) {
            const float4 a = sm_s[j][sl], c = sm_q[j][sl];
            S.x += a.x; S.y += a.y; S.z += a.z; S.w += a.w;
            Q.x += c.x; Q.y += c.y; Q.z += c.z; Q.w += c.w;
        }

        const int it  = __ldg(item_ids + b);
        const int uid = __ldg(u + b);
        float4 t   = __ldg((const float4*)(entity_emb + (size_t)it * KDIM) + sl);
        float4 usr = __ldg((const float4*)(user_emb + (size_t)uid * KDIM) + sl);

        const float tsc = renorm_scale(half_sum(t.x * t.x + t.y * t.y +
                                                t.z * t.z + t.w * t.w));
        float4 items;
        items.x = S.x * S.x - Q.x + t.x * tsc;
        items.y = S.y * S.y - Q.y + t.y * tsc;
        items.z = S.z * S.z - Q.z + t.z * tsc;
        items.w = S.w * S.w - Q.w + t.w * tsc;

        const float usc = renorm_scale(half_sum(usr.x * usr.x + usr.y * usr.y +
                                                usr.z * usr.z + usr.w * usr.w));
        const float dot = half_sum((usr.x * items.x + usr.y * items.y +
                                    usr.z * items.z + usr.w * items.w) * usc);
        if (lane == 0) out[b] = 1.0f / (1.0f + expf(-dot));
    }
}

extern "C" void kernel_launch(void* const* d_in, const int* in_sizes, int n_in,
                              void* d_out, int out_size)
{
    const float* entity_emb = (const float*)d_in[0];
    const float* user_emb   = (const float*)d_in[1];
    // d_in[2..5] = Wa, ba, Wh, bh : dead code (softmax over singleton axis == 1)
    const int* u         = (const int*)d_in[6];
    const int* item_ids  = (const int*)d_in[7];
    const int* nbr1_idx  = (const int*)d_in[8];
    const int* node_ids0 = (const int*)d_in[9];
    const int* nbr0      = (const int*)d_in[10];

    const int B  = in_sizes[6];   // 2048
    const int n0 = in_sizes[9];   // 65536

    // hop 0: one warp per node, 4 warps per block
    {
        const int wpb = 4;
        const int blocks = (n0 + wpb - 1) / wpb;
        hop0_kernel<<<blocks, wpb * 32>>>(entity_emb, node_ids0, nbr0, n0);
    }
    // hop 1: one block (4 warps) per batch row
    hop1_kernel<<<B, 128>>>(entity_emb, user_emb, u, item_ids, nbr1_idx,
                            (float*)d_out, B);
}

// round 11
// speedup vs baseline: 1.0815x; 1.0815x over previous
#include <cuda_runtime.h>
#include <math.h>

#define KDIM 64
#define DEG 32
#define N0_MAX 65536

// hop-0 aggregate scratch: 65536 x 64 f32 = 16 MB (static __device__, no alloc)
__device__ float g_agg0[N0_MAX * KDIM];

// reduce across a 16-lane half-warp (xor 8,4,2,1)
__device__ __forceinline__ float half_sum(float v) {
#pragma unroll
    for (int o = 8; o > 0; o >>= 1) v += __shfl_xor_sync(0xffffffffu, v, o);
    return v;
}
// full-warp reduce (xor 16,8,4,2,1)
__device__ __forceinline__ float warp_sum(float v) {
#pragma unroll
    for (int o = 16; o > 0; o >>= 1) v += __shfl_xor_sync(0xffffffffu, v, o);
    return v;
}

// renorm scale: min(1, 1/max(sqrt(ss), 1e-12)) == ss > 1 ? rsqrt(ss) : 1
__device__ __forceinline__ float renorm_scale(float ss) {
    return (ss > 1.0f) ? rsqrtf(ss) : 1.0f;
}

// ============================ hop 0 ============================
// R8 winner verbatim (67us measured; at the random-gather DRAM roofline).
// One warp per node; half-warp sub covers neighbors {16*sub+i}; lane sl owns
// dims [4sl,4sl+3]; all 16 rows prefetched into registers.
__global__ void __launch_bounds__(128) hop0_kernel(
    const float* __restrict__ entity_emb,
    const int* __restrict__ node_ids0,
    const int* __restrict__ nbr0,
    int n0)
{
    const int node = blockIdx.x * (blockDim.x >> 5) + (threadIdx.x >> 5);
    const int lane = threadIdx.x & 31;
    const int sub  = lane >> 4;
    const int sl   = lane & 15;
    if (node >= n0) return;

    const int myidx = __ldg(nbr0 + (size_t)node * DEG + lane);
    const int tid   = __ldg(node_ids0 + node);

    float4 e[16];
#pragma unroll
    for (int i = 0; i < 16; i++) {
        const int id = __shfl_sync(0xffffffffu, myidx, i + (sub << 4));
        e[i] = __ldg((const float4*)(entity_emb + (size_t)id * KDIM) + sl);
    }
    float4 t = __ldg((const float4*)(entity_emb + (size_t)tid * KDIM) + sl);

    float4 s = make_float4(0.f, 0.f, 0.f, 0.f);
    float4 q = make_float4(0.f, 0.f, 0.f, 0.f);
#pragma unroll
    for (int i = 0; i < 16; i++) {
        const float ss = half_sum(e[i].x * e[i].x + e[i].y * e[i].y +
                                  e[i].z * e[i].z + e[i].w * e[i].w);
        const float sc = renorm_scale(ss);
        const float ex = e[i].x * sc, ey = e[i].y * sc;
        const float ez = e[i].z * sc, ew = e[i].w * sc;
        s.x += ex; s.y += ey; s.z += ez; s.w += ew;
        q.x += ex * ex; q.y += ey * ey; q.z += ez * ez; q.w += ew * ew;
    }

    s.x += __shfl_xor_sync(0xffffffffu, s.x, 16);
    s.y += __shfl_xor_sync(0xffffffffu, s.y, 16);
    s.z += __shfl_xor_sync(0xffffffffu, s.z, 16);
    s.w += __shfl_xor_sync(0xffffffffu, s.w, 16);
    q.x += __shfl_xor_sync(0xffffffffu, q.x, 16);
    q.y += __shfl_xor_sync(0xffffffffu, q.y, 16);
    q.z += __shfl_xor_sync(0xffffffffu, q.z, 16);
    q.w += __shfl_xor_sync(0xffffffffu, q.w, 16);

    const float tsc = renorm_scale(half_sum(t.x * t.x + t.y * t.y +
                                            t.z * t.z + t.w * t.w));

    if (sub == 0) {
        float4 o;
        o.x = s.x * s.x - q.x + t.x * tsc;
        o.y = s.y * s.y - q.y + t.y * tsc;
        o.z = s.z * s.z - q.z + t.z * tsc;
        o.w = s.w * s.w - q.w + t.w * tsc;
        *((float4*)(g_agg0 + (size_t)node * KDIM) + sl) = o;
    }
}

// ============================ hop 1 ============================
// Block (4 warps) per batch row, float2 lane layout: lane owns dims
// [2*lane, 2*lane+1]; a full warp covers one agg0 row per LDG.64. Warp w
// accumulates neighbors [8w, 8w+8) with ZERO shuffles (lane-local sums).
// Warps merge via smem; the 3 reduce chains survive only in the per-block
// epilogue on warp 0.
__global__ void __launch_bounds__(128) hop1_kernel(
    const float* __restrict__ entity_emb,
    const float* __restrict__ user_emb,
    const int* __restrict__ u,
    const int* __restrict__ item_ids,
    const int* __restrict__ nbr1_idx,
    float* __restrict__ out,
    int B)
{
    __shared__ float2 sm_s[4][32];
    __shared__ float2 sm_q[4][32];

    const int b    = blockIdx.x;
    const int w    = threadIdx.x >> 5;
    const int lane = threadIdx.x & 31;
    if (b >= B) return;

    // lanes 0-7 hold this warp's 8 neighbor indices
    const int myidx = (lane < 8)
        ? __ldg(nbr1_idx + (size_t)b * DEG + w * 8 + lane) : 0;

    // 8 full-row gathers per warp (LDG.64, 256B coalesced per row)
    float2 e[8];
#pragma unroll
    for (int i = 0; i < 8; i++) {
        const int id = __shfl_sync(0xffffffffu, myidx, i);
        e[i] = *((const float2*)(g_agg0 + (size_t)id * KDIM) + lane);
    }

    float2 s = make_float2(0.f, 0.f);
    float2 q = make_float2(0.f, 0.f);
#pragma unroll
    for (int i = 0; i < 8; i++) {
        s.x += e[i].x; s.y += e[i].y;
        q.x += e[i].x * e[i].x; q.y += e[i].y * e[i].y;
    }

    sm_s[w][lane] = s;
    sm_q[w][lane] = q;
    __syncthreads();

    if (w == 0) {
        float2 S = sm_s[0][lane], Q = sm_q[0][lane];
#pragma unroll
        for (int j = 1; j < 4; j++) {
            const float2 a = sm_s[j][lane], c = sm_q[j][lane];
            S.x += a.x; S.y += a.y;
            Q.x += c.x; Q.y += c.y;
        }

        const int it  = __ldg(item_ids + b);
        const int uid = __ldg(u + b);
        const float2 t   = __ldg((const float2*)(entity_emb + (size_t)it * KDIM) + lane);
        const float2 usr = __ldg((const float2*)(user_emb + (size_t)uid * KDIM) + lane);

        const float tsc = renorm_scale(warp_sum(t.x * t.x + t.y * t.y));

        float2 items;
        items.x = S.x * S.x - Q.x + t.x * tsc;
        items.y = S.y * S.y - Q.y + t.y * tsc;

        const float usc = renorm_scale(warp_sum(usr.x * usr.x + usr.y * usr.y));
        const float dot = warp_sum(usr.x * items.x + usr.y * items.y) * usc;
        if (lane == 0) out[b] = 1.0f / (1.0f + expf(-dot));
    }
}

extern "C" void kernel_launch(void* const* d_in, const int* in_sizes, int n_in,
                              void* d_out, int out_size)
{
    const float* entity_emb = (const float*)d_in[0];
    const float* user_emb   = (const float*)d_in[1];
    // d_in[2..5] = Wa, ba, Wh, bh : dead code (softmax over singleton axis == 1)
    const int* u         = (const int*)d_in[6];
    const int* item_ids  = (const int*)d_in[7];
    const int* nbr1_idx  = (const int*)d_in[8];
    const int* node_ids0 = (const int*)d_in[9];
    const int* nbr0      = (const int*)d_in[10];

    const int B  = in_sizes[6];   // 2048
    const int n0 = in_sizes[9];   // 65536

    // hop 0: one warp per node, 4 warps per block
    {
        const int wpb = 4;
        const int blocks = (n0 + wpb - 1) / wpb;
        hop0_kernel<<<blocks, wpb * 32>>>(entity_emb, node_ids0, nbr0, n0);
    }
    // hop 1: one block (4 warps) per batch row
    hop1_kernel<<<B, 128>>>(entity_emb, user_emb, u, item_ids, nbr1_idx,
                            (float*)d_out, B);
}

// round 12
// speedup vs baseline: 1.1077x; 1.0242x over previous
#include <cuda_runtime.h>
#include <math.h>

#define KDIM 64
#define DEG 32
#define N0_MAX 65536

// hop-0 aggregate scratch: 65536 x 64 f32 = 16 MB (static __device__, no alloc)
__device__ float g_agg0[N0_MAX * KDIM];

// reduce across a 16-lane half-warp (xor 8,4,2,1)
__device__ __forceinline__ float half_sum(float v) {
#pragma unroll
    for (int o = 8; o > 0; o >>= 1) v += __shfl_xor_sync(0xffffffffu, v, o);
    return v;
}

// renorm scale: min(1, 1/max(sqrt(ss), 1e-12)) == ss > 1 ? rsqrt(ss) : 1
__device__ __forceinline__ float renorm_scale(float ss) {
    return (ss > 1.0f) ? rsqrtf(ss) : 1.0f;
}

// ============================ hop 0 ============================
// R8 winner verbatim (67us measured; at the random-gather DRAM roofline).
// One warp per node; half-warp sub covers neighbors {16*sub+i}; lane sl owns
// dims [4sl,4sl+3]; all 16 rows prefetched into registers.
__global__ void __launch_bounds__(128) hop0_kernel(
    const float* __restrict__ entity_emb,
    const int* __restrict__ node_ids0,
    const int* __restrict__ nbr0,
    int n0)
{
    const int node = blockIdx.x * (blockDim.x >> 5) + (threadIdx.x >> 5);
    const int lane = threadIdx.x & 31;
    const int sub  = lane >> 4;
    const int sl   = lane & 15;
    if (node >= n0) return;

    const int myidx = __ldg(nbr0 + (size_t)node * DEG + lane);
    const int tid   = __ldg(node_ids0 + node);

    float4 e[16];
#pragma unroll
    for (int i = 0; i < 16; i++) {
        const int id = __shfl_sync(0xffffffffu, myidx, i + (sub << 4));
        e[i] = __ldg((const float4*)(entity_emb + (size_t)id * KDIM) + sl);
    }
    float4 t = __ldg((const float4*)(entity_emb + (size_t)tid * KDIM) + sl);

    float4 s = make_float4(0.f, 0.f, 0.f, 0.f);
    float4 q = make_float4(0.f, 0.f, 0.f, 0.f);
#pragma unroll
    for (int i = 0; i < 16; i++) {
        const float ss = half_sum(e[i].x * e[i].x + e[i].y * e[i].y +
                                  e[i].z * e[i].z + e[i].w * e[i].w);
        const float sc = renorm_scale(ss);
        const float ex = e[i].x * sc, ey = e[i].y * sc;
        const float ez = e[i].z * sc, ew = e[i].w * sc;
        s.x += ex; s.y += ey; s.z += ez; s.w += ew;
        q.x += ex * ex; q.y += ey * ey; q.z += ez * ez; q.w += ew * ew;
    }

    s.x += __shfl_xor_sync(0xffffffffu, s.x, 16);
    s.y += __shfl_xor_sync(0xffffffffu, s.y, 16);
    s.z += __shfl_xor_sync(0xffffffffu, s.z, 16);
    s.w += __shfl_xor_sync(0xffffffffu, s.w, 16);
    q.x += __shfl_xor_sync(0xffffffffu, q.x, 16);
    q.y += __shfl_xor_sync(0xffffffffu, q.y, 16);
    q.z += __shfl_xor_sync(0xffffffffu, q.z, 16);
    q.w += __shfl_xor_sync(0xffffffffu, q.w, 16);

    const float tsc = renorm_scale(half_sum(t.x * t.x + t.y * t.y +
                                            t.z * t.z + t.w * t.w));

    if (sub == 0) {
        float4 o;
        o.x = s.x * s.x - q.x + t.x * tsc;
        o.y = s.y * s.y - q.y + t.y * tsc;
        o.z = s.z * s.z - q.z + t.z * tsc;
        o.w = s.w * s.w - q.w + t.w * tsc;
        *((float4*)(g_agg0 + (size_t)node * KDIM) + sl) = o;
    }
}

// ============================ hop 1 ============================
// R8 mainloop (best measured). NEW: warps 1 & 2 prefetch the item/user rows
// into smem at the TOP, so their DRAM latency overlaps the agg0 gathers and
// warp 0's epilogue reads smem instead of a serial post-sync DRAM chain.
__global__ void __launch_bounds__(128) hop1_kernel(
    const float* __restrict__ entity_emb,
    const float* __restrict__ user_emb,
    const int* __restrict__ u,
    const int* __restrict__ item_ids,
    const int* __restrict__ nbr1_idx,
    float* __restrict__ out,
    int B)
{
    __shared__ float4 sm_s[4][16];
    __shared__ float4 sm_q[4][16];
    __shared__ float4 sm_t[16];
    __shared__ float4 sm_u[16];

    const int b    = blockIdx.x;
    const int w    = threadIdx.x >> 5;
    const int lane = threadIdx.x & 31;
    const int sub  = lane >> 4;
    const int sl   = lane & 15;
    if (b >= B) return;

    // top-of-kernel prefetch: warp 1 loads item row, warp 2 loads user row
    if (w == 1 && sub == 0) {
        const int it = __ldg(item_ids + b);
        sm_t[sl] = __ldg((const float4*)(entity_emb + (size_t)it * KDIM) + sl);
    }
    if (w == 2 && sub == 0) {
        const int uid = __ldg(u + b);
        sm_u[sl] = __ldg((const float4*)(user_emb + (size_t)uid * KDIM) + sl);
    }

    // lanes 0-7 hold this warp's 8 neighbor indices
    const int myidx = (lane < 8)
        ? __ldg(nbr1_idx + (size_t)b * DEG + w * 8 + lane) : 0;

    float4 e[4];
#pragma unroll
    for (int i = 0; i < 4; i++) {
        const int id = __shfl_sync(0xffffffffu, myidx, (sub << 2) + i);
        e[i] = *((const float4*)(g_agg0 + (size_t)id * KDIM) + sl);
    }

    float4 s = make_float4(0.f, 0.f, 0.f, 0.f);
    float4 q = make_float4(0.f, 0.f, 0.f, 0.f);
#pragma unroll
    for (int i = 0; i < 4; i++) {
        s.x += e[i].x; s.y += e[i].y; s.z += e[i].z; s.w += e[i].w;
        q.x += e[i].x * e[i].x; q.y += e[i].y * e[i].y;
        q.z += e[i].z * e[i].z; q.w += e[i].w * e[i].w;
    }

    s.x += __shfl_xor_sync(0xffffffffu, s.x, 16);
    s.y += __shfl_xor_sync(0xffffffffu, s.y, 16);
    s.z += __shfl_xor_sync(0xffffffffu, s.z, 16);
    s.w += __shfl_xor_sync(0xffffffffu, s.w, 16);
    q.x += __shfl_xor_sync(0xffffffffu, q.x, 16);
    q.y += __shfl_xor_sync(0xffffffffu, q.y, 16);
    q.z += __shfl_xor_sync(0xffffffffu, q.z, 16);
    q.w += __shfl_xor_sync(0xffffffffu, q.w, 16);

    if (sub == 0) { sm_s[w][sl] = s; sm_q[w][sl] = q; }
    __syncthreads();

    if (w == 0) {
        float4 S = sm_s[0][sl], Q = sm_q[0][sl];
#pragma unroll
        for (int j = 1; j < 4; j++) {
            const float4 a = sm_s[j][sl], c = sm_q[j][sl];
            S.x += a.x; S.y += a.y; S.z += a.z; S.w += a.w;
            Q.x += c.x; Q.y += c.y; Q.z += c.z; Q.w += c.w;
        }

        const float4 t   = sm_t[sl];
        const float4 usr = sm_u[sl];

        const float tsc = renorm_scale(half_sum(t.x * t.x + t.y * t.y +
                                                t.z * t.z + t.w * t.w));
        float4 items;
        items.x = S.x * S.x - Q.x + t.x * tsc;
        items.y = S.y * S.y - Q.y + t.y * tsc;
        items.z = S.z * S.z - Q.z + t.z * tsc;
        items.w = S.w * S.w - Q.w + t.w * tsc;

        const float usc = renorm_scale(half_sum(usr.x * usr.x + usr.y * usr.y +
                                                usr.z * usr.z + usr.w * usr.w));
        const float dot = half_sum((usr.x * items.x + usr.y * items.y +
                                    usr.z * items.z + usr.w * items.w) * usc);
        if (lane == 0) out[b] = 1.0f / (1.0f + expf(-dot));
    }
}

extern "C" void kernel_launch(void* const* d_in, const int* in_sizes, int n_in,
                              void* d_out, int out_size)
{
    const float* entity_emb = (const float*)d_in[0];
    const float* user_emb   = (const float*)d_in[1];
    // d_in[2..5] = Wa, ba, Wh, bh : dead code (softmax over singleton axis == 1)
    const int* u         = (const int*)d_in[6];
    const int* item_ids  = (const int*)d_in[7];
    const int* nbr1_idx  = (const int*)d_in[8];
    const int* node_ids0 = (const int*)d_in[9];
    const int* nbr0      = (const int*)d_in[10];

    const int B  = in_sizes[6];   // 2048
    const int n0 = in_sizes[9];   // 65536

    // hop 0: one warp per node, 4 warps per block
    {
        const int wpb = 4;
        const int blocks = (n0 + wpb - 1) / wpb;
        hop0_kernel<<<blocks, wpb * 32>>>(entity_emb, node_ids0, nbr0, n0);
    }
    // hop 1: one block (4 warps) per batch row
    hop1_kernel<<<B, 128>>>(entity_emb, user_emb, u, item_ids, nbr1_idx,
                            (float*)d_out, B);
}